// round 16
// baseline (speedup 1.0000x reference)
#include <cuda_runtime.h>
#include <cstdint>
#include <math.h>

#define D_MODEL 1024
#define NHEAD   16
#define DK      64
#define BATCH   2
#define NQ      2048
#define NKV     2048

// Scratch (allocation-free)
__device__ float g_Q[BATCH * NQ * D_MODEL];
__device__ float g_attn[BATCH * NQ * D_MODEL];

__device__ __forceinline__ float to_tf32(float x) {
    float r; asm("cvt.rna.tf32.f32 %0, %1;" : "=f"(r) : "f"(x));
    return r;
}
__device__ __forceinline__ uint32_t tf32u(float x) {
    return __float_as_uint(to_tf32(x));
}
__device__ __forceinline__ float ex2f(float x) {
    float r; asm("ex2.approx.f32 %0, %1;" : "=f"(r) : "f"(x)); return r;
}

// m16n8k8 tf32 mma (sm_80+ path; compiles for plain sm_103)
__device__ __forceinline__ void mma_tf32(float* c, const uint32_t* a,
                                         uint32_t b0, uint32_t b1) {
    asm volatile(
        "mma.sync.aligned.m16n8k8.row.col.f32.tf32.tf32.f32 "
        "{%0,%1,%2,%3},{%4,%5,%6,%7},{%8,%9},{%0,%1,%2,%3};"
        : "+f"(c[0]), "+f"(c[1]), "+f"(c[2]), "+f"(c[3])
        : "r"(a[0]), "r"(a[1]), "r"(a[2]), "r"(a[3]), "r"(b0), "r"(b1));
}

// ldmatrix x4: four 8x8 b16 matrices (= 8x4 b32 tiles). Lane L of matrix m
// receives b32 element [L/4][L%4]; address groups lanes 0-7 -> m0, etc.
__device__ __forceinline__ void ldsm_x4(uint32_t& r0, uint32_t& r1,
                                        uint32_t& r2, uint32_t& r3,
                                        uint32_t addr) {
    asm volatile("ldmatrix.sync.aligned.m8n8.x4.shared.b16 {%0,%1,%2,%3}, [%4];"
                 : "=r"(r0), "=r"(r1), "=r"(r2), "=r"(r3) : "r"(addr));
}

// ----------------------------------------------------------------------------
// Tensor-core GEMM, tf32x1, warp tile 64x64 (mt=4, nt=8).
// A-fragments now via LDSM.x4 (1 issue per mt per ks instead of 4 LDS).
// Block 128 threads (4 warps, 2x2), block tile 128x128, K-chunk 16.
// Strides: A 20 (LDSM rows: bank-quad 5r distinct), B 136 (banks 8tg+g).
// ----------------------------------------------------------------------------
__global__ __launch_bounds__(128, 2) void gemm_tc(const float* __restrict__ A,
                                                  const float* __restrict__ B,
                                                  float* __restrict__ C,
                                                  int M, int N, int K)
{
    __shared__ float Ash[128][20];   // A (tf32)
    __shared__ float Bsh[16][136];   // B (tf32)

    const int tid  = threadIdx.x;
    const int warp = tid >> 5;
    const int lane = tid & 31;
    const int g    = lane >> 2;
    const int tg   = lane & 3;
    const int wm   = (warp & 1) * 64;
    const int wn   = (warp >> 1) * 64;
    const int cRow = blockIdx.y * 128;
    const int cCol = blockIdx.x * 128;

    const int ar  = tid >> 2;
    const int ac4 = (tid & 3) * 4;
    const int br  = tid >> 5;
    const int bc4 = (tid & 31) * 4;

    // LDSM lane address parts for A fragments (a0..a3 = rowlo/rowhi x collo/colhi)
    const uint32_t ash_base = (uint32_t)__cvta_generic_to_shared(&Ash[0][0]);
    const int lr = ((lane >> 3) & 1) * 8 + (lane & 7);   // row within 16-block
    const int lc = (lane >> 4) * 4;                       // col half

    float cacc[4][8][4];
#pragma unroll
    for (int mt = 0; mt < 4; mt++)
#pragma unroll
        for (int nt = 0; nt < 8; nt++)
#pragma unroll
            for (int j = 0; j < 4; j++) cacc[mt][nt][j] = 0.f;

    float4 pa[4], pb[4];
#pragma unroll
    for (int i = 0; i < 4; i++) {
        pa[i] = *(const float4*)&A[(size_t)(cRow + ar + i * 32) * K + ac4];
        pb[i] = *(const float4*)&B[(size_t)(br + i * 4) * N + cCol + bc4];
    }

    const int NC = K / 16;
    for (int kc = 0; kc < NC; kc++) {
        {
            float4 hv;
#define CVT4(src, dsth) \
            hv.x = to_tf32(src.x); hv.y = to_tf32(src.y); \
            hv.z = to_tf32(src.z); hv.w = to_tf32(src.w); \
            *(float4*)&dsth = hv;
#pragma unroll
            for (int i = 0; i < 4; i++) {
                CVT4(pa[i], Ash[ar + i * 32][ac4]);
                CVT4(pb[i], Bsh[br + i * 4][bc4]);
            }
#undef CVT4
        }
        __syncthreads();

        if (kc + 1 < NC) {
            int k0 = (kc + 1) * 16;
#pragma unroll
            for (int i = 0; i < 4; i++) {
                pa[i] = *(const float4*)&A[(size_t)(cRow + ar + i * 32) * K + k0 + ac4];
                pb[i] = *(const float4*)&B[(size_t)(k0 + br + i * 4) * N + cCol + bc4];
            }
        }

#pragma unroll
        for (int ks = 0; ks < 2; ks++) {
            const int k8 = ks * 8;
            uint32_t ah[4][4];
#pragma unroll
            for (int mt = 0; mt < 4; mt++) {
                uint32_t addr = ash_base +
                    (uint32_t)(((wm + mt * 16 + lr) * 20 + k8 + lc) * 4);
                ldsm_x4(ah[mt][0], ah[mt][1], ah[mt][2], ah[mt][3], addr);
            }
#pragma unroll
            for (int nt = 0; nt < 8; nt++) {
                int n0 = wn + nt * 8 + g;
                uint32_t bh0 = __float_as_uint(Bsh[k8 + tg][n0]);
                uint32_t bh1 = __float_as_uint(Bsh[k8 + tg + 4][n0]);
#pragma unroll
                for (int mt = 0; mt < 4; mt++)
                    mma_tf32(cacc[mt][nt], ah[mt], bh0, bh1);
            }
        }
        __syncthreads();
    }

#pragma unroll
    for (int mt = 0; mt < 4; mt++) {
        int row0 = cRow + wm + mt * 16 + g;
#pragma unroll
        for (int nt = 0; nt < 8; nt++) {
            int col = cCol + wn + nt * 8 + 2 * tg;
            *(float2*)&C[(size_t)row0 * N + col]       = make_float2(cacc[mt][nt][0], cacc[mt][nt][1]);
            *(float2*)&C[(size_t)(row0 + 8) * N + col] = make_float2(cacc[mt][nt][2], cacc[mt][nt][3]);
        }
    }
}

// ----------------------------------------------------------------------------
// Tensor-core attention (tf32 mma, exp-without-max), warp tile 32q x 64kv.
// K-fragments (QK) and P-fragments (PV) via LDSM.x4; V stays scalar LDS
// (transposed orientation). Block 128 threads, q-tile 128, kv-tile 64.
// ----------------------------------------------------------------------------
struct AttnSmem {
    uint32_t Ks[64][68];
    uint32_t Vs[64][72];
    uint32_t Ps[128][68];
    float    kvsel[64];
    float    vred[64];
};

__global__ __launch_bounds__(128, 2) void attn_mma(
    const float* __restrict__ Q,
    const float* __restrict__ Kin,
    const float* __restrict__ Vin,
    const unsigned* __restrict__ kvmask,
    const unsigned* __restrict__ qmask,
    float* __restrict__ attn)
{
    extern __shared__ AttnSmem smem_raw[];
    AttnSmem& s = smem_raw[0];

    const int tid  = threadIdx.x;
    const int warp = tid >> 5;
    const int lane = tid & 31;
    const int g    = lane >> 2;
    const int tg   = lane & 3;
    const int b    = blockIdx.z;
    const int h    = blockIdx.y;
    const int q0   = blockIdx.x * 128;
    const int qb   = warp * 32;
    const float C2 = 0.18033688011112042f;   // 0.125 * log2(e)

    const uint32_t ks_base = (uint32_t)__cvta_generic_to_shared(&s.Ks[0][0]);
    const uint32_t ps_base = (uint32_t)__cvta_generic_to_shared(&s.Ps[0][0]);
    // QK kb lane parts: m0=(nt,collo) m1=(nt,colhi) m2=(nt+1,collo) m3=(nt+1,colhi)
    const int krow = (lane >> 4) * 8 + (lane & 7);
    const int kcol = ((lane >> 3) & 1) * 4;
    // PV pa lane parts: m0=(rowlo,collo) m1=(rowhi,collo) m2=(rowlo,colhi) m3=(rowhi,colhi)
    const int prow = ((lane >> 3) & 1) * 8 + (lane & 7);
    const int pcol = (lane >> 4) * 4;

    // ---- Q fragments for 2 m-tiles, resident in regs ----
    uint32_t qf[2][8][4];
    {
        const float* qp = Q + (size_t)(b * NQ + q0 + qb) * D_MODEL + h * DK;
#pragma unroll
        for (int mt = 0; mt < 2; mt++)
#pragma unroll
            for (int ks = 0; ks < 8; ks++) {
                qf[mt][ks][0] = tf32u(qp[(size_t)(mt * 16 + g)     * D_MODEL + 8 * ks + tg]);
                qf[mt][ks][1] = tf32u(qp[(size_t)(mt * 16 + g + 8) * D_MODEL + 8 * ks + tg]);
                qf[mt][ks][2] = tf32u(qp[(size_t)(mt * 16 + g)     * D_MODEL + 8 * ks + tg + 4]);
                qf[mt][ks][3] = tf32u(qp[(size_t)(mt * 16 + g + 8) * D_MODEL + 8 * ks + tg + 4]);
            }
    }

    float of[2][8][4];
#pragma unroll
    for (int mt = 0; mt < 2; mt++)
#pragma unroll
        for (int nt = 0; nt < 8; nt++)
#pragma unroll
            for (int j = 0; j < 4; j++) of[mt][nt][j] = 0.f;
    float lr2[2][2] = {{0.f, 0.f}, {0.f, 0.f}};
    float4 vsum = make_float4(0.f, 0.f, 0.f, 0.f);

    if (tid < 64) s.vred[tid] = 0.f;

    const float* Kb = Kin + (size_t)(b * NHEAD + h) * NKV * DK;
    const float* Vb = Vin + (size_t)(b * NHEAD + h) * NKV * DK;
    const int c4 = (tid & 15) * 4;
    const int r0 = tid >> 4;

    for (int t = 0; t < NKV / 64; t++) {
        const int k0 = t * 64;
        __syncthreads();

        // ---- stage K/V tile (tf32) ----
#pragma unroll
        for (int i = 0; i < 8; i++) {
            int r = r0 + i * 8;
            float4 k4 = *(const float4*)&Kb[(size_t)(k0 + r) * DK + c4];
            uint4 ku = make_uint4(tf32u(k4.x), tf32u(k4.y), tf32u(k4.z), tf32u(k4.w));
            *(uint4*)&s.Ks[r][c4] = ku;
            float4 v4 = *(const float4*)&Vb[(size_t)(k0 + r) * DK + c4];
            vsum.x += v4.x; vsum.y += v4.y; vsum.z += v4.z; vsum.w += v4.w;
            uint4 vu = make_uint4(tf32u(v4.x), tf32u(v4.y), tf32u(v4.z), tf32u(v4.w));
            *(uint4*)&s.Vs[r][c4] = vu;
        }
        if (tid < 64)
            s.kvsel[tid] = (kvmask[b * NKV + k0 + tid] != 0u) ? 0.f : -1e9f;
        __syncthreads();

        // ---- S = Q K^T (K fragments via LDSM.x4, nt-pairs) ----
        float sc[2][8][4];
#pragma unroll
        for (int mt = 0; mt < 2; mt++)
#pragma unroll
            for (int nt = 0; nt < 8; nt++)
#pragma unroll
                for (int j = 0; j < 4; j++) sc[mt][nt][j] = 0.f;
#pragma unroll
        for (int ks = 0; ks < 8; ks++) {
            const int k8 = ks * 8;
#pragma unroll
            for (int np = 0; np < 4; np++) {
                uint32_t kb0, kb1, kb2, kb3;
                uint32_t addr = ks_base +
                    (uint32_t)(((np * 16 + krow) * 68 + k8 + kcol) * 4);
                ldsm_x4(kb0, kb1, kb2, kb3, addr);
                mma_tf32(sc[0][2 * np],     qf[0][ks], kb0, kb1);
                mma_tf32(sc[1][2 * np],     qf[1][ks], kb0, kb1);
                mma_tf32(sc[0][2 * np + 1], qf[0][ks], kb2, kb3);
                mma_tf32(sc[1][2 * np + 1], qf[1][ks], kb2, kb3);
            }
        }

        // ---- epilogue: p = 2^(s*C2 + sel), accumulate l, store P (tf32) ----
#pragma unroll
        for (int nt = 0; nt < 8; nt++) {
            float s0 = s.kvsel[8 * nt + 2 * tg];
            float s1 = s.kvsel[8 * nt + 2 * tg + 1];
#pragma unroll
            for (int mt = 0; mt < 2; mt++) {
                float p0 = ex2f(fmaf(sc[mt][nt][0], C2, s0));
                float p1 = ex2f(fmaf(sc[mt][nt][1], C2, s1));
                float p2 = ex2f(fmaf(sc[mt][nt][2], C2, s0));
                float p3 = ex2f(fmaf(sc[mt][nt][3], C2, s1));
                lr2[mt][0] += p0 + p1;
                lr2[mt][1] += p2 + p3;
                uint2 w0 = make_uint2(tf32u(p0), tf32u(p1));
                uint2 w1 = make_uint2(tf32u(p2), tf32u(p3));
                *(uint2*)&s.Ps[qb + mt * 16 + g][8 * nt + 2 * tg]     = w0;
                *(uint2*)&s.Ps[qb + mt * 16 + g + 8][8 * nt + 2 * tg] = w1;
            }
        }
        __syncwarp();   // Ps is warp-private

        // ---- O += P V (P fragments via LDSM.x4) ----
#pragma unroll
        for (int ks = 0; ks < 8; ks++) {
            const int k8 = ks * 8;
            uint32_t pa[2][4];
#pragma unroll
            for (int mt = 0; mt < 2; mt++) {
                uint32_t addr = ps_base +
                    (uint32_t)(((qb + mt * 16 + prow) * 68 + k8 + pcol) * 4);
                ldsm_x4(pa[mt][0], pa[mt][1], pa[mt][2], pa[mt][3], addr);
            }
#pragma unroll
            for (int nt = 0; nt < 8; nt++) {
                uint32_t vb0 = s.Vs[8 * ks + tg][8 * nt + g];
                uint32_t vb1 = s.Vs[8 * ks + tg + 4][8 * nt + g];
                mma_tf32(of[0][nt], pa[0], vb0, vb1);
                mma_tf32(of[1][nt], pa[1], vb0, vb1);
            }
        }
    }

    // ---- mean(V) reduction for masked q rows ----
    atomicAdd(&s.vred[c4 + 0], vsum.x);
    atomicAdd(&s.vred[c4 + 1], vsum.y);
    atomicAdd(&s.vred[c4 + 2], vsum.z);
    atomicAdd(&s.vred[c4 + 3], vsum.w);
    __syncthreads();

    // ---- l reduction across quad lanes; output ----
#pragma unroll
    for (int mt = 0; mt < 2; mt++) {
#pragma unroll
        for (int hf = 0; hf < 2; hf++) {
            lr2[mt][hf] += __shfl_xor_sync(0xffffffffu, lr2[mt][hf], 1);
            lr2[mt][hf] += __shfl_xor_sync(0xffffffffu, lr2[mt][hf], 2);
        }
    }
    const float u = 1.f / 2048.f;
#pragma unroll
    for (int mt = 0; mt < 2; mt++) {
        const float inv0 = 1.f / lr2[mt][0];
        const float inv1 = 1.f / lr2[mt][1];
        const bool qok0 = (qmask[b * NQ + q0 + qb + mt * 16 + g]     != 0u);
        const bool qok1 = (qmask[b * NQ + q0 + qb + mt * 16 + g + 8] != 0u);
        float* op0 = attn + (size_t)(b * NQ + q0 + qb + mt * 16 + g)     * D_MODEL + h * DK;
        float* op1 = attn + (size_t)(b * NQ + q0 + qb + mt * 16 + g + 8) * D_MODEL + h * DK;
#pragma unroll
        for (int nt = 0; nt < 8; nt++) {
            int d = 8 * nt + 2 * tg;
            float2 o0, o1;
            if (qok0) { o0.x = of[mt][nt][0] * inv0; o0.y = of[mt][nt][1] * inv0; }
            else      { o0.x = s.vred[d] * u;        o0.y = s.vred[d + 1] * u; }
            if (qok1) { o1.x = of[mt][nt][2] * inv1; o1.y = of[mt][nt][3] * inv1; }
            else      { o1.x = s.vred[d] * u;        o1.y = s.vred[d + 1] * u; }
            *(float2*)&op0[d] = o0;
            *(float2*)&op1[d] = o1;
        }
    }
}

// ----------------------------------------------------------------------------
// Inputs (metadata order): x, K, V, Wq, Wo, kv_pad_mask, q_pad_mask
// ----------------------------------------------------------------------------
extern "C" void kernel_launch(void* const* d_in, const int* in_sizes, int n_in,
                              void* d_out, int out_size)
{
    const float*    x   = (const float*)d_in[0];
    const float*    K   = (const float*)d_in[1];
    const float*    V   = (const float*)d_in[2];
    const float*    Wq  = (const float*)d_in[3];
    const float*    Wo  = (const float*)d_in[4];
    const unsigned* kvm = (const unsigned*)d_in[5];
    const unsigned* qm  = (const unsigned*)d_in[6];
    float*          out = (float*)d_out;

    float *gQ, *gA;
    cudaGetSymbolAddress((void**)&gQ, g_Q);
    cudaGetSymbolAddress((void**)&gA, g_attn);

    const int M = BATCH * NQ;
    dim3 gemm_grid(D_MODEL / 128, M / 128);

    const int ATTN_SMEM = (int)sizeof(AttnSmem);
    cudaFuncSetAttribute(attn_mma, cudaFuncAttributeMaxDynamicSharedMemorySize, ATTN_SMEM);

    gemm_tc<<<gemm_grid, 128>>>(x, Wq, gQ, M, D_MODEL, D_MODEL);

    dim3 attn_grid(NQ / 128, NHEAD, BATCH);
    attn_mma<<<attn_grid, 128, ATTN_SMEM>>>(gQ, K, V, kvm, qm, gA);

    gemm_tc<<<gemm_grid, 128>>>(gA, Wo, out, M, D_MODEL, D_MODEL);
}

// round 17
// speedup vs baseline: 2.1277x; 2.1277x over previous
#include <cuda_runtime.h>
#include <cuda_fp16.h>
#include <cstdint>
#include <math.h>

#define D_MODEL 1024
#define NHEAD   16
#define DK      64
#define BATCH   2
#define NQ      2048
#define NKV     2048

// Scratch (allocation-free)
__device__ float g_Q[BATCH * NQ * D_MODEL];
__device__ float g_attn[BATCH * NQ * D_MODEL];

__device__ __forceinline__ float ex2f(float x) {
    float r; asm("ex2.approx.f32 %0, %1;" : "=f"(r) : "f"(x)); return r;
}
// pack two fp32 -> fp16x2 (lo = first/even-k element)
__device__ __forceinline__ uint32_t pack_h2(float lo, float hi) {
    __half2 h = __floats2half2_rn(lo, hi);
    return *reinterpret_cast<uint32_t*>(&h);
}

// m16n8k16 fp16 mma, fp32 accumulate (sm_80+ path; compiles for plain sm_103)
__device__ __forceinline__ void mma_f16(float* c, const uint32_t* a,
                                        uint32_t b0, uint32_t b1) {
    asm volatile(
        "mma.sync.aligned.m16n8k16.row.col.f32.f16.f16.f32 "
        "{%0,%1,%2,%3},{%4,%5,%6,%7},{%8,%9},{%0,%1,%2,%3};"
        : "+f"(c[0]), "+f"(c[1]), "+f"(c[2]), "+f"(c[3])
        : "r"(a[0]), "r"(a[1]), "r"(a[2]), "r"(a[3]), "r"(b0), "r"(b1));
}

// ----------------------------------------------------------------------------
// Tensor-core GEMM, fp16 m16n8k16 (fp32 accum). Warp tile 64x64 (mt=4, nt=8).
// Block 128 threads (4 warps, 2x2), block tile 128x128, K-chunk 16 (1 k16 step).
// Smem fp16x2-packed along k. Strides: A 12 words (banks 12g+tg distinct),
// B 136 (8tg+g distinct). Register prefetch, convert+pack at staging.
// ----------------------------------------------------------------------------
__global__ __launch_bounds__(128, 2) void gemm_tc(const float* __restrict__ A,
                                                  const float* __restrict__ B,
                                                  float* __restrict__ C,
                                                  int M, int N, int K)
{
    __shared__ uint32_t Ash[128][12];   // [m][k/2] fp16x2 (8 used)
    __shared__ uint32_t Bsh[8][136];    // [k/2][n] fp16x2 (128 used)

    const int tid  = threadIdx.x;
    const int warp = tid >> 5;
    const int lane = tid & 31;
    const int g    = lane >> 2;
    const int tg   = lane & 3;
    const int wm   = (warp & 1) * 64;
    const int wn   = (warp >> 1) * 64;
    const int cRow = blockIdx.y * 128;
    const int cCol = blockIdx.x * 128;

    const int ar  = tid >> 2;         // A rows ar + {0,32,64,96}
    const int ac4 = (tid & 3) * 4;    // A k-col group (0,4,8,12)
    const int brp = tid >> 5;         // B k-pair base: pairs brp + {0,4}
    const int bc4 = (tid & 31) * 4;   // B n-col group

    float cacc[4][8][4];
#pragma unroll
    for (int mt = 0; mt < 4; mt++)
#pragma unroll
        for (int nt = 0; nt < 8; nt++)
#pragma unroll
            for (int j = 0; j < 4; j++) cacc[mt][nt][j] = 0.f;

    // prefetch chunk 0
    float4 pa[4], pb[4];
#pragma unroll
    for (int i = 0; i < 4; i++)
        pa[i] = *(const float4*)&A[(size_t)(cRow + ar + i * 32) * K + ac4];
#pragma unroll
    for (int i = 0; i < 2; i++) {
        int rp = brp + i * 4;
        pb[2 * i]     = *(const float4*)&B[(size_t)(2 * rp) * N + cCol + bc4];
        pb[2 * i + 1] = *(const float4*)&B[(size_t)(2 * rp + 1) * N + cCol + bc4];
    }

    const int NC = K / 16;
    for (int kc = 0; kc < NC; kc++) {
        // ---- stage: convert fp32 -> fp16x2 packed ----
#pragma unroll
        for (int i = 0; i < 4; i++) {
            Ash[ar + i * 32][ac4 / 2]     = pack_h2(pa[i].x, pa[i].y);
            Ash[ar + i * 32][ac4 / 2 + 1] = pack_h2(pa[i].z, pa[i].w);
        }
#pragma unroll
        for (int i = 0; i < 2; i++) {
            int rp = brp + i * 4;
            Bsh[rp][bc4 + 0] = pack_h2(pb[2 * i].x, pb[2 * i + 1].x);
            Bsh[rp][bc4 + 1] = pack_h2(pb[2 * i].y, pb[2 * i + 1].y);
            Bsh[rp][bc4 + 2] = pack_h2(pb[2 * i].z, pb[2 * i + 1].z);
            Bsh[rp][bc4 + 3] = pack_h2(pb[2 * i].w, pb[2 * i + 1].w);
        }
        __syncthreads();

        // prefetch next chunk while mma runs
        if (kc + 1 < NC) {
            int k0 = (kc + 1) * 16;
#pragma unroll
            for (int i = 0; i < 4; i++)
                pa[i] = *(const float4*)&A[(size_t)(cRow + ar + i * 32) * K + k0 + ac4];
#pragma unroll
            for (int i = 0; i < 2; i++) {
                int rp = brp + i * 4;
                pb[2 * i]     = *(const float4*)&B[(size_t)(k0 + 2 * rp) * N + cCol + bc4];
                pb[2 * i + 1] = *(const float4*)&B[(size_t)(k0 + 2 * rp + 1) * N + cCol + bc4];
            }
        }

        // ---- one k16 mma step ----
        uint32_t ah[4][4];
#pragma unroll
        for (int mt = 0; mt < 4; mt++) {
            int m0 = wm + mt * 16 + g;
            ah[mt][0] = Ash[m0][tg];
            ah[mt][1] = Ash[m0 + 8][tg];
            ah[mt][2] = Ash[m0][tg + 4];
            ah[mt][3] = Ash[m0 + 8][tg + 4];
        }
#pragma unroll
        for (int nt = 0; nt < 8; nt++) {
            int n0 = wn + nt * 8 + g;
            uint32_t bh0 = Bsh[tg][n0];
            uint32_t bh1 = Bsh[tg + 4][n0];
#pragma unroll
            for (int mt = 0; mt < 4; mt++)
                mma_f16(cacc[mt][nt], ah[mt], bh0, bh1);
        }
        __syncthreads();
    }

#pragma unroll
    for (int mt = 0; mt < 4; mt++) {
        int row0 = cRow + wm + mt * 16 + g;
#pragma unroll
        for (int nt = 0; nt < 8; nt++) {
            int col = cCol + wn + nt * 8 + 2 * tg;
            *(float2*)&C[(size_t)row0 * N + col]       = make_float2(cacc[mt][nt][0], cacc[mt][nt][1]);
            *(float2*)&C[(size_t)(row0 + 8) * N + col] = make_float2(cacc[mt][nt][2], cacc[mt][nt][3]);
        }
    }
}

// ----------------------------------------------------------------------------
// Tensor-core attention, fp16 m16n8k16 (fp32 accum), exp-without-max.
// Warp tile 32q x 64kv (mt=2). Block 128 threads, q-tile 128, kv-tile 64.
// Ksp [kv][dk/2] stride 36 (banks 4g+tg); Vsp [kv/2][d] stride 72 (8tg+g);
// Psp [q][kv/2] stride 36 (4g+tg).
// ----------------------------------------------------------------------------
struct AttnSmem {
    uint32_t Ks[64][36];    // fp16x2 packed along dk (32 used)
    uint32_t Vs[32][72];    // fp16x2 packed along kv pairs (64 used)
    uint32_t Ps[128][36];   // fp16x2 packed along kv (32 used)
    float    kvsel[64];
    float    vred[64];
};

__global__ __launch_bounds__(128, 2) void attn_mma(
    const float* __restrict__ Q,
    const float* __restrict__ Kin,
    const float* __restrict__ Vin,
    const unsigned* __restrict__ kvmask,
    const unsigned* __restrict__ qmask,
    float* __restrict__ attn)
{
    extern __shared__ AttnSmem smem_raw[];
    AttnSmem& s = smem_raw[0];

    const int tid  = threadIdx.x;
    const int warp = tid >> 5;
    const int lane = tid & 31;
    const int g    = lane >> 2;
    const int tg   = lane & 3;
    const int b    = blockIdx.z;
    const int h    = blockIdx.y;
    const int q0   = blockIdx.x * 128;
    const int qb   = warp * 32;
    const float C2 = 0.18033688011112042f;   // 0.125 * log2(e)

    // ---- Q fragments (fp16x2), 2 m-tiles x 4 k16-steps, resident in regs ----
    uint32_t qf[2][4][4];
    {
        const float* qp = Q + (size_t)(b * NQ + q0 + qb) * D_MODEL + h * DK;
#pragma unroll
        for (int mt = 0; mt < 2; mt++)
#pragma unroll
            for (int ks = 0; ks < 4; ks++) {
                const float* r0p = qp + (size_t)(mt * 16 + g) * D_MODEL;
                const float* r1p = qp + (size_t)(mt * 16 + g + 8) * D_MODEL;
                float2 v0 = *(const float2*)&r0p[16 * ks + 2 * tg];
                float2 v1 = *(const float2*)&r1p[16 * ks + 2 * tg];
                float2 v2 = *(const float2*)&r0p[16 * ks + 2 * tg + 8];
                float2 v3 = *(const float2*)&r1p[16 * ks + 2 * tg + 8];
                qf[mt][ks][0] = pack_h2(v0.x, v0.y);
                qf[mt][ks][1] = pack_h2(v1.x, v1.y);
                qf[mt][ks][2] = pack_h2(v2.x, v2.y);
                qf[mt][ks][3] = pack_h2(v3.x, v3.y);
            }
    }

    float of[2][8][4];
#pragma unroll
    for (int mt = 0; mt < 2; mt++)
#pragma unroll
        for (int nt = 0; nt < 8; nt++)
#pragma unroll
            for (int j = 0; j < 4; j++) of[mt][nt][j] = 0.f;
    float lr2[2][2] = {{0.f, 0.f}, {0.f, 0.f}};
    float4 vsum = make_float4(0.f, 0.f, 0.f, 0.f);

    if (tid < 64) s.vred[tid] = 0.f;

    const float* Kb = Kin + (size_t)(b * NHEAD + h) * NKV * DK;
    const float* Vb = Vin + (size_t)(b * NHEAD + h) * NKV * DK;
    const int c4 = (tid & 15) * 4;   // dk col group (staging)
    const int r0 = tid >> 4;         // row base 0..7 (staging)

    for (int t = 0; t < NKV / 64; t++) {
        const int k0 = t * 64;
        __syncthreads();

        // ---- stage K (packed along dk) ----
#pragma unroll
        for (int i = 0; i < 8; i++) {
            int r = r0 + i * 8;
            float4 k4 = *(const float4*)&Kb[(size_t)(k0 + r) * DK + c4];
            s.Ks[r][c4 / 2]     = pack_h2(k4.x, k4.y);
            s.Ks[r][c4 / 2 + 1] = pack_h2(k4.z, k4.w);
        }
        // ---- stage V (packed along kv pairs) ----
#pragma unroll
        for (int i = 0; i < 4; i++) {
            int rp = r0 + i * 8;     // kv-pair index 0..31
            float4 v0 = *(const float4*)&Vb[(size_t)(k0 + 2 * rp) * DK + c4];
            float4 v1 = *(const float4*)&Vb[(size_t)(k0 + 2 * rp + 1) * DK + c4];
            vsum.x += v0.x + v1.x; vsum.y += v0.y + v1.y;
            vsum.z += v0.z + v1.z; vsum.w += v0.w + v1.w;
            s.Vs[rp][c4 + 0] = pack_h2(v0.x, v1.x);
            s.Vs[rp][c4 + 1] = pack_h2(v0.y, v1.y);
            s.Vs[rp][c4 + 2] = pack_h2(v0.z, v1.z);
            s.Vs[rp][c4 + 3] = pack_h2(v0.w, v1.w);
        }
        if (tid < 64)
            s.kvsel[tid] = (kvmask[b * NKV + k0 + tid] != 0u) ? 0.f : -1e9f;
        __syncthreads();

        // ---- S = Q K^T (4 k16 steps) ----
        float sc[2][8][4];
#pragma unroll
        for (int mt = 0; mt < 2; mt++)
#pragma unroll
            for (int nt = 0; nt < 8; nt++)
#pragma unroll
                for (int j = 0; j < 4; j++) sc[mt][nt][j] = 0.f;
#pragma unroll
        for (int ks = 0; ks < 4; ks++) {
#pragma unroll
            for (int nt = 0; nt < 8; nt++) {
                int n0 = 8 * nt + g;
                uint32_t kb0 = s.Ks[n0][8 * ks + tg];
                uint32_t kb1 = s.Ks[n0][8 * ks + tg + 4];
                mma_f16(sc[0][nt], qf[0][ks], kb0, kb1);
                mma_f16(sc[1][nt], qf[1][ks], kb0, kb1);
            }
        }

        // ---- epilogue: p = 2^(s*C2 + sel), accumulate l, store P (fp16x2) ----
#pragma unroll
        for (int nt = 0; nt < 8; nt++) {
            float s0 = s.kvsel[8 * nt + 2 * tg];
            float s1 = s.kvsel[8 * nt + 2 * tg + 1];
#pragma unroll
            for (int mt = 0; mt < 2; mt++) {
                float p0 = ex2f(fmaf(sc[mt][nt][0], C2, s0));
                float p1 = ex2f(fmaf(sc[mt][nt][1], C2, s1));
                float p2 = ex2f(fmaf(sc[mt][nt][2], C2, s0));
                float p3 = ex2f(fmaf(sc[mt][nt][3], C2, s1));
                lr2[mt][0] += p0 + p1;
                lr2[mt][1] += p2 + p3;
                s.Ps[qb + mt * 16 + g][4 * nt + tg]     = pack_h2(p0, p1);
                s.Ps[qb + mt * 16 + g + 8][4 * nt + tg] = pack_h2(p2, p3);
            }
        }
        __syncwarp();   // Ps is warp-private

        // ---- O += P V (4 k16 steps over kv) ----
#pragma unroll
        for (int ks = 0; ks < 4; ks++) {
            uint32_t pa[2][4];
#pragma unroll
            for (int mt = 0; mt < 2; mt++) {
                pa[mt][0] = s.Ps[qb + mt * 16 + g][8 * ks + tg];
                pa[mt][1] = s.Ps[qb + mt * 16 + g + 8][8 * ks + tg];
                pa[mt][2] = s.Ps[qb + mt * 16 + g][8 * ks + tg + 4];
                pa[mt][3] = s.Ps[qb + mt * 16 + g + 8][8 * ks + tg + 4];
            }
#pragma unroll
            for (int nt = 0; nt < 8; nt++) {
                int n0 = 8 * nt + g;
                uint32_t vb0 = s.Vs[8 * ks + tg][n0];
                uint32_t vb1 = s.Vs[8 * ks + tg + 4][n0];
                mma_f16(of[0][nt], pa[0], vb0, vb1);
                mma_f16(of[1][nt], pa[1], vb0, vb1);
            }
        }
    }

    // ---- mean(V) reduction for masked q rows ----
    atomicAdd(&s.vred[c4 + 0], vsum.x);
    atomicAdd(&s.vred[c4 + 1], vsum.y);
    atomicAdd(&s.vred[c4 + 2], vsum.z);
    atomicAdd(&s.vred[c4 + 3], vsum.w);
    __syncthreads();

    // ---- l reduction across quad lanes; output ----
#pragma unroll
    for (int mt = 0; mt < 2; mt++) {
#pragma unroll
        for (int hf = 0; hf < 2; hf++) {
            lr2[mt][hf] += __shfl_xor_sync(0xffffffffu, lr2[mt][hf], 1);
            lr2[mt][hf] += __shfl_xor_sync(0xffffffffu, lr2[mt][hf], 2);
        }
    }
    const float u = 1.f / 2048.f;
#pragma unroll
    for (int mt = 0; mt < 2; mt++) {
        const float inv0 = 1.f / lr2[mt][0];
        const float inv1 = 1.f / lr2[mt][1];
        const bool qok0 = (qmask[b * NQ + q0 + qb + mt * 16 + g]     != 0u);
        const bool qok1 = (qmask[b * NQ + q0 + qb + mt * 16 + g + 8] != 0u);
        float* op0 = attn + (size_t)(b * NQ + q0 + qb + mt * 16 + g)     * D_MODEL + h * DK;
        float* op1 = attn + (size_t)(b * NQ + q0 + qb + mt * 16 + g + 8) * D_MODEL + h * DK;
#pragma unroll
        for (int nt = 0; nt < 8; nt++) {
            int d = 8 * nt + 2 * tg;
            float2 o0, o1;
            if (qok0) { o0.x = of[mt][nt][0] * inv0; o0.y = of[mt][nt][1] * inv0; }
            else      { o0.x = s.vred[d] * u;        o0.y = s.vred[d + 1] * u; }
            if (qok1) { o1.x = of[mt][nt][2] * inv1; o1.y = of[mt][nt][3] * inv1; }
            else      { o1.x = s.vred[d] * u;        o1.y = s.vred[d + 1] * u; }
            *(float2*)&op0[d] = o0;
            *(float2*)&op1[d] = o1;
        }
    }
}

// ----------------------------------------------------------------------------
// Inputs (metadata order): x, K, V, Wq, Wo, kv_pad_mask, q_pad_mask
// ----------------------------------------------------------------------------
extern "C" void kernel_launch(void* const* d_in, const int* in_sizes, int n_in,
                              void* d_out, int out_size)
{
    const float*    x   = (const float*)d_in[0];
    const float*    K   = (const float*)d_in[1];
    const float*    V   = (const float*)d_in[2];
    const float*    Wq  = (const float*)d_in[3];
    const float*    Wo  = (const float*)d_in[4];
    const unsigned* kvm = (const unsigned*)d_in[5];
    const unsigned* qm  = (const unsigned*)d_in[6];
    float*          out = (float*)d_out;

    float *gQ, *gA;
    cudaGetSymbolAddress((void**)&gQ, g_Q);
    cudaGetSymbolAddress((void**)&gA, g_attn);

    const int M = BATCH * NQ;
    dim3 gemm_grid(D_MODEL / 128, M / 128);

    const int ATTN_SMEM = (int)sizeof(AttnSmem);
    cudaFuncSetAttribute(attn_mma, cudaFuncAttributeMaxDynamicSharedMemorySize, ATTN_SMEM);

    gemm_tc<<<gemm_grid, 128>>>(x, Wq, gQ, M, D_MODEL, D_MODEL);

    dim3 attn_grid(NQ / 128, NHEAD, BATCH);
    attn_mma<<<attn_grid, 128, ATTN_SMEM>>>(gQ, K, V, kvm, qm, gA);

    gemm_tc<<<gemm_grid, 128>>>(gA, Wo, out, M, D_MODEL, D_MODEL);
}